// round 5
// baseline (speedup 1.0000x reference)
#include <cuda_runtime.h>
#include <math.h>
#include <stdint.h>

#define L_LEVELS 16
#define TBL (1 << 19)
#define TMASK (TBL - 1)
#define BLOCK 128

struct Scales { float s[L_LEVELS]; };

__device__ __forceinline__ float relu(float x) { return fmaxf(x, 0.0f); }

// Gather the two dim-0 corner entries {i0, i1} of one outer corner.
// Always: LDG.128 at the aligned even/odd pair containing i0 (covers i0 and i0^1).
// If i1 happens to BE i0^1 (g0 even / i0 even), we're done. Otherwise a single
// predicated LDG.64 fetches i1 (inline PTX so ptxas emits @p LDG, not BSSY).
__device__ __forceinline__ void gather_pair(const float2* __restrict__ gt,
                                            uint32_t i0, uint32_t i1,
                                            float w0, float w1,
                                            float& f0, float& f1) {
    const float4* p0 = reinterpret_cast<const float4*>(gt + (i0 & ~1u));
    float4 v = __ldg(p0);
    bool odd = (i0 & 1u) != 0u;
    float e0x = odd ? v.z : v.x;
    float e0y = odd ? v.w : v.y;
    float e1x = odd ? v.x : v.z;   // entry at i0^1
    float e1y = odd ? v.y : v.w;
    uint32_t partner = i0 ^ 1u;
    const float2* p1 = gt + i1;
    asm("{ .reg .pred p; setp.ne.u32 p, %2, %3; @p ld.global.nc.v2.f32 {%0,%1}, [%4]; }"
        : "+f"(e1x), "+f"(e1y)
        : "r"(i1), "r"(partner), "l"(p1));
    f0 = fmaf(w0, e0x, f0);
    f0 = fmaf(w1, e1x, f0);
    f1 = fmaf(w0, e0y, f1);
    f1 = fmaf(w1, e1y, f1);
}

// Dense level: idx = sum corner*stride (provably <= T-1, clamp is a no-op:
// max gi+1 = res-1 per dim -> max idx = res^4-1 <= T-1 when res^4 <= T)
template <int R>
__device__ __forceinline__ void enc_level_dense(const float in4[4], float scale,
                                                const float2* __restrict__ gt,
                                                float& o0, float& o1) {
    float fr[4], omf[4];
    int k0[4], k1[4];
    const int S[4] = {1, R, R * R, R * R * R};
#pragma unroll
    for (int d = 0; d < 4; d++) {
        float p = in4[d] * scale + 0.5f;
        float g = floorf(p);
        fr[d] = p - g;
        omf[d] = 1.0f - fr[d];
        int gi = (int)g;
        k0[d] = gi * S[d];
        k1[d] = k0[d] + S[d];
    }
    float f0 = 0.0f, f1 = 0.0f;
#pragma unroll
    for (int c = 0; c < 8; c++) {  // corners over dims 1..3
        int B = ((c & 1) ? k1[1] : k0[1]) + ((c & 2) ? k1[2] : k0[2]) +
                ((c & 4) ? k1[3] : k0[3]);
        float wo = ((c & 1) ? fr[1] : omf[1]) * ((c & 2) ? fr[2] : omf[2]) *
                   ((c & 4) ? fr[3] : omf[3]);
        uint32_t i0 = (uint32_t)(B + k0[0]);
        uint32_t i1 = (uint32_t)(B + k1[0]);
        gather_pair(gt, i0, i1, wo * omf[0], wo * fr[0], f0, f1);
    }
    o0 = f0;
    o1 = f1;
}

// Hash level: idx = (c0*1 ^ c1*P1 ^ c2*P2 ^ c3*P3) & (T-1); P0 == 1 so the two
// dim-0 corners differ by XOR of g0^(g0+1); when g0 even that's exactly bit 0.
__device__ __forceinline__ void enc_level_hash(const float in4[4], float scale,
                                               const float2* __restrict__ gt,
                                               float& o0, float& o1) {
    const uint32_t P[4] = {1u, 2654435761u, 805459861u, 3674351687u};
    float fr[4], omf[4];
    uint32_t k0[4], k1[4];
#pragma unroll
    for (int d = 0; d < 4; d++) {
        float p = in4[d] * scale + 0.5f;
        float g = floorf(p);
        fr[d] = p - g;
        omf[d] = 1.0f - fr[d];
        uint32_t gi = (uint32_t)(int)g;
        k0[d] = gi * P[d];
        k1[d] = k0[d] + P[d];
    }
    float f0 = 0.0f, f1 = 0.0f;
#pragma unroll
    for (int c = 0; c < 8; c++) {  // corners over dims 1..3
        uint32_t H = (((c & 1) ? k1[1] : k0[1]) ^ ((c & 2) ? k1[2] : k0[2]) ^
                      ((c & 4) ? k1[3] : k0[3]));
        float wo = ((c & 1) ? fr[1] : omf[1]) * ((c & 2) ? fr[2] : omf[2]) *
                   ((c & 4) ? fr[3] : omf[3]);
        uint32_t i0 = (H ^ k0[0]) & TMASK;
        uint32_t i1 = (H ^ k1[0]) & TMASK;
        gather_pair(gt, i0, i1, wo * omf[0], wo * fr[0], f0, f1);
    }
    o0 = f0;
    o1 = f1;
}

__global__ void __launch_bounds__(BLOCK, 4)
htrf_kernel(const float4* __restrict__ xyzs,   // [N,4]
            const float* __restrict__ dirs,    // [N,3]
            const float2* __restrict__ grid,   // [L,T] of float2
            const float4* __restrict__ gW1,    // [64,32] -> 512 float4
            const float* __restrict__ gW2,     // [16,64]
            const float4* __restrict__ gWc1,   // [64,32] -> 512 float4
            const float* __restrict__ gWc2,    // [64,64]
            const float* __restrict__ gWc3,    // [3,64]
            float* __restrict__ out,           // [N*3 color | N sigma]
            int N, Scales sc) {
    // All weights stored so inner loops read contiguous float4 broadcasts.
    __shared__ float4 sW1[64 * 8];    // row-major rows of W1
    __shared__ float4 sW2T[64 * 4];   // sW2T[k*4+q] = W2[4q..4q+3][k]
    __shared__ float4 sWc1[64 * 8];
    __shared__ float4 sWc2T[64 * 16]; // sWc2T[k*16+q] = Wc2[4q..4q+3][k]
    __shared__ float4 sWc3T[64];      // {Wc3[0][k], Wc3[1][k], Wc3[2][k], 0}

    for (int i = threadIdx.x; i < 512; i += BLOCK) sW1[i] = gW1[i];
    for (int i = threadIdx.x; i < 512; i += BLOCK) sWc1[i] = gWc1[i];
    for (int i = threadIdx.x; i < 16 * 64; i += BLOCK) {
        int j = i >> 6, k = i & 63;
        ((float*)sW2T)[k * 16 + j] = gW2[i];
    }
    for (int i = threadIdx.x; i < 64 * 64; i += BLOCK) {
        int j = i >> 6, k = i & 63;
        ((float*)sWc2T)[k * 64 + j] = gWc2[i];
    }
    for (int i = threadIdx.x; i < 256; i += BLOCK) {
        int k = i >> 2, j = i & 3;
        ((float*)sWc3T)[i] = (j < 3) ? gWc3[j * 64 + k] : 0.0f;
    }
    __syncthreads();

    int t = blockIdx.x * BLOCK + threadIdx.x;
    if (t >= N) return;

    float4 xin = __ldg(&xyzs[t]);
    float in4[4];
    in4[0] = (xin.x + 1.0f) * 0.5f;
    in4[1] = (xin.y + 1.0f) * 0.5f;
    in4[2] = (xin.z + 1.0f) * 0.5f;
    in4[3] = xin.w;

    // ---- hash encode: hr[32] ----
    float hr[32];
    enc_level_dense<8>(in4, sc.s[0], grid + 0 * TBL, hr[0], hr[1]);
    enc_level_dense<12>(in4, sc.s[1], grid + 1 * TBL, hr[2], hr[3]);
    enc_level_dense<17>(in4, sc.s[2], grid + 2 * TBL, hr[4], hr[5]);
    enc_level_dense<25>(in4, sc.s[3], grid + 3 * TBL, hr[6], hr[7]);
#pragma unroll
    for (int l = 4; l < L_LEVELS; l++) {
        enc_level_hash(in4, sc.s[l], grid + l * TBL, hr[2 * l], hr[2 * l + 1]);
    }

    // ---- density MLP: h16 = relu(hr @ W1^T) @ W2^T (fused) ----
    float h16[16];
#pragma unroll
    for (int j = 0; j < 16; j++) h16[j] = 0.0f;
    for (int k = 0; k < 64; k++) {
        float v = 0.0f;
        const float4* w1row = &sW1[k * 8];
#pragma unroll
        for (int q = 0; q < 8; q++) {
            float4 w = w1row[q];
            v = fmaf(hr[4 * q + 0], w.x, v);
            v = fmaf(hr[4 * q + 1], w.y, v);
            v = fmaf(hr[4 * q + 2], w.z, v);
            v = fmaf(hr[4 * q + 3], w.w, v);
        }
        v = relu(v);
        const float4* w2col = &sW2T[k * 4];
#pragma unroll
        for (int q = 0; q < 4; q++) {
            float4 w = w2col[q];
            h16[4 * q + 0] = fmaf(v, w.x, h16[4 * q + 0]);
            h16[4 * q + 1] = fmaf(v, w.y, h16[4 * q + 1]);
            h16[4 * q + 2] = fmaf(v, w.z, h16[4 * q + 2]);
            h16[4 * q + 3] = fmaf(v, w.w, h16[4 * q + 3]);
        }
    }
    float sigma = __expf(h16[0]);

    // ---- spherical harmonics deg 4 ----
    float dx = __ldg(&dirs[3 * t + 0]) * 2.0f - 1.0f;
    float dy = __ldg(&dirs[3 * t + 1]) * 2.0f - 1.0f;
    float dz = __ldg(&dirs[3 * t + 2]) * 2.0f - 1.0f;
    float xy = dx * dy, xz = dx * dz, yz = dy * dz;
    float x2 = dx * dx, y2 = dy * dy, z2 = dz * dz;
    float sh[16];
    sh[0] = 0.28209479177387814f;
    sh[1] = -0.48860251190291987f * dy;
    sh[2] = 0.48860251190291987f * dz;
    sh[3] = -0.48860251190291987f * dx;
    sh[4] = 1.0925484305920792f * xy;
    sh[5] = -1.0925484305920792f * yz;
    sh[6] = 0.94617469575756f * z2 - 0.31539156525252f;
    sh[7] = -1.0925484305920792f * xz;
    sh[8] = 0.5462742152960396f * x2 - 0.5462742152960396f * y2;
    sh[9] = 0.5900435899266435f * dy * (-3.0f * x2 + y2);
    sh[10] = 2.890611442640554f * xy * dz;
    sh[11] = 0.4570457994644657f * dy * (1.0f - 5.0f * z2);
    sh[12] = 0.3731763325901154f * dz * (5.0f * z2 - 3.0f);
    sh[13] = 0.4570457994644657f * dx * (1.0f - 5.0f * z2);
    sh[14] = 1.445305721320277f * dz * (x2 - y2);
    sh[15] = 0.5900435899266435f * dx * (-x2 + 3.0f * y2);

    // ---- color MLP: ci=[sh,h16]; a2 = relu(ci@Wc1^T)@Wc2^T (fused) ----
    float a2[64];
#pragma unroll
    for (int j = 0; j < 64; j++) a2[j] = 0.0f;
    for (int k = 0; k < 64; k++) {
        float v = 0.0f;
        const float4* wrow = &sWc1[k * 8];
#pragma unroll
        for (int q = 0; q < 4; q++) {
            float4 w = wrow[q];
            v = fmaf(sh[4 * q + 0], w.x, v);
            v = fmaf(sh[4 * q + 1], w.y, v);
            v = fmaf(sh[4 * q + 2], w.z, v);
            v = fmaf(sh[4 * q + 3], w.w, v);
        }
#pragma unroll
        for (int q = 0; q < 4; q++) {
            float4 w = wrow[4 + q];
            v = fmaf(h16[4 * q + 0], w.x, v);
            v = fmaf(h16[4 * q + 1], w.y, v);
            v = fmaf(h16[4 * q + 2], w.z, v);
            v = fmaf(h16[4 * q + 3], w.w, v);
        }
        v = relu(v);
        const float4* wc2col = &sWc2T[k * 16];
#pragma unroll
        for (int q = 0; q < 16; q++) {
            float4 w = wc2col[q];
            a2[4 * q + 0] = fmaf(v, w.x, a2[4 * q + 0]);
            a2[4 * q + 1] = fmaf(v, w.y, a2[4 * q + 1]);
            a2[4 * q + 2] = fmaf(v, w.z, a2[4 * q + 2]);
            a2[4 * q + 3] = fmaf(v, w.w, a2[4 * q + 3]);
        }
    }
    float c0 = 0.0f, c1 = 0.0f, c2 = 0.0f;
#pragma unroll
    for (int k = 0; k < 64; k++) {
        float v = relu(a2[k]);
        float4 w = sWc3T[k];
        c0 = fmaf(v, w.x, c0);
        c1 = fmaf(v, w.y, c1);
        c2 = fmaf(v, w.z, c2);
    }
    c0 = 1.0f / (1.0f + __expf(-c0));
    c1 = 1.0f / (1.0f + __expf(-c1));
    c2 = 1.0f / (1.0f + __expf(-c2));

    out[t * 3 + 0] = c0;
    out[t * 3 + 1] = c1;
    out[t * 3 + 2] = c2;
    out[3 * N + t] = sigma;
}

extern "C" void kernel_launch(void* const* d_in, const int* in_sizes, int n_in,
                              void* d_out, int out_size) {
    const float4* xyzs = (const float4*)d_in[0];
    const float* dirs = (const float*)d_in[1];
    const float2* grid = (const float2*)d_in[2];
    const float4* W1 = (const float4*)d_in[3];
    const float* W2 = (const float*)d_in[4];
    const float4* Wc1 = (const float4*)d_in[5];
    const float* Wc2 = (const float*)d_in[6];
    const float* Wc3 = (const float*)d_in[7];
    float* out = (float*)d_out;

    int N = in_sizes[0] / 4;

    Scales sc;
    const double log2B = log(2048.0 / 8.0) / 15.0 / log(2.0);  // = 8/15
    for (int l = 0; l < L_LEVELS; l++) {
        double scale = exp2((double)l * log2B) * 8.0 - 1.0;
        sc.s[l] = (float)scale;
    }

    int blocks = (N + BLOCK - 1) / BLOCK;
    htrf_kernel<<<blocks, BLOCK>>>(xyzs, dirs, grid, W1, W2, Wc1, Wc2, Wc3,
                                   out, N, sc);
}

// round 6
// speedup vs baseline: 1.3901x; 1.3901x over previous
#include <cuda_runtime.h>
#include <math.h>
#include <stdint.h>

#define L_LEVELS 16
#define TBL (1 << 19)
#define TMASK (TBL - 1)
#define BLOCK 128

// Constant-memory weight bank (separate HW port from L1tex, which the random
// hash-grid gathers saturate). Layout (floats):
//   [0,2048)    W1   row-major [64,32]
//   [2048,3072) W2T  [k*16+j] = W2[j*64+k]
//   [3072,5120) Wc1  row-major [64,32]
//   [5120,9216) Wc2T [k*64+j] = Wc2[j*64+k]
//   [9216,9472) Wc3T [k*4+j]  = Wc3[j*64+k] (j<3), 0 pad
#define CW_TOTAL 9472
__constant__ float cW[CW_TOTAL];
__device__ float g_scratch[CW_TOTAL];

struct Scales { float s[L_LEVELS]; };

__device__ __forceinline__ float relu(float x) { return fmaxf(x, 0.0f); }

__global__ void prep_kernel(const float* __restrict__ W1,
                            const float* __restrict__ W2,
                            const float* __restrict__ Wc1,
                            const float* __restrict__ Wc2,
                            const float* __restrict__ Wc3) {
    int i = blockIdx.x * blockDim.x + threadIdx.x;  // 0..4095
    if (i < 2048) g_scratch[i] = W1[i];
    if (i < 1024) { int k = i >> 4, j = i & 15; g_scratch[2048 + i] = W2[j * 64 + k]; }
    if (i < 2048) g_scratch[3072 + i] = Wc1[i];
    if (i < 4096) { int k = i >> 6, j = i & 63; g_scratch[5120 + i] = Wc2[j * 64 + k]; }
    if (i < 256)  { int k = i >> 2, j = i & 3;  g_scratch[9216 + i] = (j < 3) ? Wc3[j * 64 + k] : 0.0f; }
}

// Dense level: idx = min(sum corner*stride, T-1)
template <int R>
__device__ __forceinline__ void enc_level_dense(const float in4[4], float scale,
                                                const float2* __restrict__ gt,
                                                float& o0, float& o1) {
    float fr[4], omf[4];
    int k0[4], k1[4];
    const int S[4] = {1, R, R * R, R * R * R};
#pragma unroll
    for (int d = 0; d < 4; d++) {
        float p = in4[d] * scale + 0.5f;
        float g = floorf(p);
        fr[d] = p - g;
        omf[d] = 1.0f - fr[d];
        int gi = (int)g;
        k0[d] = gi * S[d];
        k1[d] = k0[d] + S[d];
    }
    float f0 = 0.0f, f1 = 0.0f;
#pragma unroll
    for (int c = 0; c < 16; c++) {
        int idx = ((c & 1) ? k1[0] : k0[0]) + ((c & 2) ? k1[1] : k0[1]) +
                  ((c & 4) ? k1[2] : k0[2]) + ((c & 8) ? k1[3] : k0[3]);
        idx = min(idx, TMASK);
        float w = ((c & 1) ? fr[0] : omf[0]) * ((c & 2) ? fr[1] : omf[1]) *
                  ((c & 4) ? fr[2] : omf[2]) * ((c & 8) ? fr[3] : omf[3]);
        float2 v = __ldg(&gt[idx]);
        f0 = fmaf(w, v.x, f0);
        f1 = fmaf(w, v.y, f1);
    }
    o0 = f0;
    o1 = f1;
}

// Hash level: idx = (c0*P0 ^ c1*P1 ^ c2*P2 ^ c3*P3) & (T-1)
__device__ __forceinline__ void enc_level_hash(const float in4[4], float scale,
                                               const float2* __restrict__ gt,
                                               float& o0, float& o1) {
    const uint32_t P[4] = {1u, 2654435761u, 805459861u, 3674351687u};
    float fr[4], omf[4];
    uint32_t k0[4], k1[4];
#pragma unroll
    for (int d = 0; d < 4; d++) {
        float p = in4[d] * scale + 0.5f;
        float g = floorf(p);
        fr[d] = p - g;
        omf[d] = 1.0f - fr[d];
        uint32_t gi = (uint32_t)(int)g;
        k0[d] = gi * P[d];
        k1[d] = k0[d] + P[d];
    }
    float f0 = 0.0f, f1 = 0.0f;
#pragma unroll
    for (int c = 0; c < 16; c++) {
        uint32_t h = (((c & 1) ? k1[0] : k0[0]) ^ ((c & 2) ? k1[1] : k0[1]) ^
                      ((c & 4) ? k1[2] : k0[2]) ^ ((c & 8) ? k1[3] : k0[3]));
        uint32_t idx = h & TMASK;
        float w = ((c & 1) ? fr[0] : omf[0]) * ((c & 2) ? fr[1] : omf[1]) *
                  ((c & 4) ? fr[2] : omf[2]) * ((c & 8) ? fr[3] : omf[3]);
        float2 v = __ldg(&gt[idx]);
        f0 = fmaf(w, v.x, f0);
        f1 = fmaf(w, v.y, f1);
    }
    o0 = f0;
    o1 = f1;
}

__global__ void __launch_bounds__(BLOCK, 4)
htrf_kernel(const float4* __restrict__ xyzs,   // [N,4]
            const float* __restrict__ dirs,    // [N,3]
            const float2* __restrict__ grid,   // [L,T] of float2
            float* __restrict__ out,           // [N*3 color | N sigma]
            int N, Scales sc) {
    const float4* __restrict__ w1   = reinterpret_cast<const float4*>(cW);          // 64 rows x 8
    const float4* __restrict__ w2t  = reinterpret_cast<const float4*>(cW + 2048);   // 64 x 4
    const float4* __restrict__ wc1  = reinterpret_cast<const float4*>(cW + 3072);   // 64 rows x 8
    const float4* __restrict__ wc2t = reinterpret_cast<const float4*>(cW + 5120);   // 64 x 16
    const float4* __restrict__ wc3t = reinterpret_cast<const float4*>(cW + 9216);   // 64

    int t = blockIdx.x * BLOCK + threadIdx.x;
    if (t >= N) return;

    float4 xin = __ldg(&xyzs[t]);
    float in4[4];
    in4[0] = (xin.x + 1.0f) * 0.5f;
    in4[1] = (xin.y + 1.0f) * 0.5f;
    in4[2] = (xin.z + 1.0f) * 0.5f;
    in4[3] = xin.w;

    // ---- hash encode: hr[32] ----
    float hr[32];
    enc_level_dense<8>(in4, sc.s[0], grid + 0 * TBL, hr[0], hr[1]);
    enc_level_dense<12>(in4, sc.s[1], grid + 1 * TBL, hr[2], hr[3]);
    enc_level_dense<17>(in4, sc.s[2], grid + 2 * TBL, hr[4], hr[5]);
    enc_level_dense<25>(in4, sc.s[3], grid + 3 * TBL, hr[6], hr[7]);
#pragma unroll
    for (int l = 4; l < L_LEVELS; l++) {
        enc_level_hash(in4, sc.s[l], grid + l * TBL, hr[2 * l], hr[2 * l + 1]);
    }

    // ---- density MLP: h16 = relu(hr @ W1^T) @ W2^T (fused, k-loop rolled) ----
    float h16[16];
#pragma unroll
    for (int j = 0; j < 16; j++) h16[j] = 0.0f;
#pragma unroll 1
    for (int k = 0; k < 64; k++) {
        float v = 0.0f;
#pragma unroll
        for (int q = 0; q < 8; q++) {
            float4 w = w1[k * 8 + q];
            v = fmaf(hr[4 * q + 0], w.x, v);
            v = fmaf(hr[4 * q + 1], w.y, v);
            v = fmaf(hr[4 * q + 2], w.z, v);
            v = fmaf(hr[4 * q + 3], w.w, v);
        }
        v = relu(v);
#pragma unroll
        for (int q = 0; q < 4; q++) {
            float4 w = w2t[k * 4 + q];
            h16[4 * q + 0] = fmaf(v, w.x, h16[4 * q + 0]);
            h16[4 * q + 1] = fmaf(v, w.y, h16[4 * q + 1]);
            h16[4 * q + 2] = fmaf(v, w.z, h16[4 * q + 2]);
            h16[4 * q + 3] = fmaf(v, w.w, h16[4 * q + 3]);
        }
    }
    float sigma = __expf(h16[0]);

    // ---- spherical harmonics deg 4 ----
    float dx = __ldg(&dirs[3 * t + 0]) * 2.0f - 1.0f;
    float dy = __ldg(&dirs[3 * t + 1]) * 2.0f - 1.0f;
    float dz = __ldg(&dirs[3 * t + 2]) * 2.0f - 1.0f;
    float xy = dx * dy, xz = dx * dz, yz = dy * dz;
    float x2 = dx * dx, y2 = dy * dy, z2 = dz * dz;
    float sh[16];
    sh[0] = 0.28209479177387814f;
    sh[1] = -0.48860251190291987f * dy;
    sh[2] = 0.48860251190291987f * dz;
    sh[3] = -0.48860251190291987f * dx;
    sh[4] = 1.0925484305920792f * xy;
    sh[5] = -1.0925484305920792f * yz;
    sh[6] = 0.94617469575756f * z2 - 0.31539156525252f;
    sh[7] = -1.0925484305920792f * xz;
    sh[8] = 0.5462742152960396f * x2 - 0.5462742152960396f * y2;
    sh[9] = 0.5900435899266435f * dy * (-3.0f * x2 + y2);
    sh[10] = 2.890611442640554f * xy * dz;
    sh[11] = 0.4570457994644657f * dy * (1.0f - 5.0f * z2);
    sh[12] = 0.3731763325901154f * dz * (5.0f * z2 - 3.0f);
    sh[13] = 0.4570457994644657f * dx * (1.0f - 5.0f * z2);
    sh[14] = 1.445305721320277f * dz * (x2 - y2);
    sh[15] = 0.5900435899266435f * dx * (-x2 + 3.0f * y2);

    // ---- color MLP: ci=[sh,h16]; a2 = relu(ci@Wc1^T)@Wc2^T (fused, rolled) ----
    float a2[64];
#pragma unroll
    for (int j = 0; j < 64; j++) a2[j] = 0.0f;
#pragma unroll 1
    for (int k = 0; k < 64; k++) {
        float v = 0.0f;
#pragma unroll
        for (int q = 0; q < 4; q++) {
            float4 w = wc1[k * 8 + q];
            v = fmaf(sh[4 * q + 0], w.x, v);
            v = fmaf(sh[4 * q + 1], w.y, v);
            v = fmaf(sh[4 * q + 2], w.z, v);
            v = fmaf(sh[4 * q + 3], w.w, v);
        }
#pragma unroll
        for (int q = 0; q < 4; q++) {
            float4 w = wc1[k * 8 + 4 + q];
            v = fmaf(h16[4 * q + 0], w.x, v);
            v = fmaf(h16[4 * q + 1], w.y, v);
            v = fmaf(h16[4 * q + 2], w.z, v);
            v = fmaf(h16[4 * q + 3], w.w, v);
        }
        v = relu(v);
#pragma unroll
        for (int q = 0; q < 16; q++) {
            float4 w = wc2t[k * 16 + q];
            a2[4 * q + 0] = fmaf(v, w.x, a2[4 * q + 0]);
            a2[4 * q + 1] = fmaf(v, w.y, a2[4 * q + 1]);
            a2[4 * q + 2] = fmaf(v, w.z, a2[4 * q + 2]);
            a2[4 * q + 3] = fmaf(v, w.w, a2[4 * q + 3]);
        }
    }
    float c0 = 0.0f, c1 = 0.0f, c2 = 0.0f;
#pragma unroll 1
    for (int k = 0; k < 64; k++) {
        float v = relu(a2[k]);
        float4 w = wc3t[k];
        c0 = fmaf(v, w.x, c0);
        c1 = fmaf(v, w.y, c1);
        c2 = fmaf(v, w.z, c2);
    }
    c0 = 1.0f / (1.0f + __expf(-c0));
    c1 = 1.0f / (1.0f + __expf(-c1));
    c2 = 1.0f / (1.0f + __expf(-c2));

    out[t * 3 + 0] = c0;
    out[t * 3 + 1] = c1;
    out[t * 3 + 2] = c2;
    out[3 * N + t] = sigma;
}

extern "C" void kernel_launch(void* const* d_in, const int* in_sizes, int n_in,
                              void* d_out, int out_size) {
    const float4* xyzs = (const float4*)d_in[0];
    const float* dirs = (const float*)d_in[1];
    const float2* grid = (const float2*)d_in[2];
    const float* W1 = (const float*)d_in[3];
    const float* W2 = (const float*)d_in[4];
    const float* Wc1 = (const float*)d_in[5];
    const float* Wc2 = (const float*)d_in[6];
    const float* Wc3 = (const float*)d_in[7];
    float* out = (float*)d_out;

    int N = in_sizes[0] / 4;

    Scales sc;
    const double log2B = log(2048.0 / 8.0) / 15.0 / log(2.0);  // = 8/15
    for (int l = 0; l < L_LEVELS; l++) {
        double scale = exp2((double)l * log2B) * 8.0 - 1.0;
        sc.s[l] = (float)scale;
    }

    // 1) transpose/pack weights into device scratch
    prep_kernel<<<16, 256>>>(W1, W2, Wc1, Wc2, Wc3);

    // 2) D2D copy into the constant bank (graph-capturable memcpy node)
    void* scratch_addr = nullptr;
    cudaGetSymbolAddress(&scratch_addr, g_scratch);
    cudaMemcpyToSymbolAsync(cW, scratch_addr, CW_TOTAL * sizeof(float), 0,
                            cudaMemcpyDeviceToDevice, 0);

    // 3) main fused kernel
    int blocks = (N + BLOCK - 1) / BLOCK;
    htrf_kernel<<<blocks, BLOCK>>>(xyzs, dirs, grid, out, N, sc);
}

// round 7
// speedup vs baseline: 1.4612x; 1.0511x over previous
#include <cuda_runtime.h>
#include <math.h>
#include <stdint.h>

#define L_LEVELS 16
#define TBL (1 << 19)
#define TMASK (TBL - 1)
#define BLOCK 128

// Constant-memory weight bank. Layout (floats):
//   [0,2048)    W1   row-major [64,32]
//   [2048,3072) W2T  [k*16+j] = W2[j*64+k]
//   [3072,5120) Wc1  row-major [64,32]
//   [5120,9216) Wc2T [k*64+j] = Wc2[j*64+k]
//   [9216,9472) Wc3T [k*4+j]  = Wc3[j*64+k] (j<3), 0 pad
#define CW_TOTAL 9472
__constant__ float cW[CW_TOTAL];
__device__ float g_scratch[CW_TOTAL];

struct Scales { float s[L_LEVELS]; };

typedef unsigned long long u64;

__device__ __forceinline__ float relu(float x) { return fmaxf(x, 0.0f); }

// packed f32x2 helpers (sm_103a dual-FMA; only reachable via PTX)
__device__ __forceinline__ void fma2(u64& d, u64 a, u64 b) {
    asm("fma.rn.f32x2 %0, %1, %2, %0;" : "+l"(d) : "l"(a), "l"(b));
}
__device__ __forceinline__ u64 pack2(float lo, float hi) {
    u64 r;
    asm("mov.b64 %0, {%1, %2};" : "=l"(r) : "f"(lo), "f"(hi));
    return r;
}
__device__ __forceinline__ void unpack2(u64 v, float& lo, float& hi) {
    asm("mov.b64 {%0, %1}, %2;" : "=f"(lo), "=f"(hi) : "l"(v));
}

__global__ void prep_kernel(const float* __restrict__ W1,
                            const float* __restrict__ W2,
                            const float* __restrict__ Wc1,
                            const float* __restrict__ Wc2,
                            const float* __restrict__ Wc3) {
    int i = blockIdx.x * blockDim.x + threadIdx.x;  // 0..4095
    if (i < 2048) g_scratch[i] = W1[i];
    if (i < 1024) { int k = i >> 4, j = i & 15; g_scratch[2048 + i] = W2[j * 64 + k]; }
    if (i < 2048) g_scratch[3072 + i] = Wc1[i];
    if (i < 4096) { int k = i >> 6, j = i & 63; g_scratch[5120 + i] = Wc2[j * 64 + k]; }
    if (i < 256)  { int k = i >> 2, j = i & 3;  g_scratch[9216 + i] = (j < 3) ? Wc3[j * 64 + k] : 0.0f; }
}

// Dense level: idx = min(sum corner*stride, T-1)
template <int R>
__device__ __forceinline__ void enc_level_dense(const float in4[4], float scale,
                                                const float2* __restrict__ gt,
                                                float& o0, float& o1) {
    float fr[4], omf[4];
    int k0[4], k1[4];
    const int S[4] = {1, R, R * R, R * R * R};
#pragma unroll
    for (int d = 0; d < 4; d++) {
        float p = in4[d] * scale + 0.5f;
        float g = floorf(p);
        fr[d] = p - g;
        omf[d] = 1.0f - fr[d];
        int gi = (int)g;
        k0[d] = gi * S[d];
        k1[d] = k0[d] + S[d];
    }
    float f0 = 0.0f, f1 = 0.0f;
#pragma unroll
    for (int c = 0; c < 16; c++) {
        int idx = ((c & 1) ? k1[0] : k0[0]) + ((c & 2) ? k1[1] : k0[1]) +
                  ((c & 4) ? k1[2] : k0[2]) + ((c & 8) ? k1[3] : k0[3]);
        idx = min(idx, TMASK);
        float w = ((c & 1) ? fr[0] : omf[0]) * ((c & 2) ? fr[1] : omf[1]) *
                  ((c & 4) ? fr[2] : omf[2]) * ((c & 8) ? fr[3] : omf[3]);
        float2 v = __ldg(&gt[idx]);
        f0 = fmaf(w, v.x, f0);
        f1 = fmaf(w, v.y, f1);
    }
    o0 = f0;
    o1 = f1;
}

// Hash level: idx = (c0*P0 ^ c1*P1 ^ c2*P2 ^ c3*P3) & (T-1)
__device__ __forceinline__ void enc_level_hash(const float in4[4], float scale,
                                               const float2* __restrict__ gt,
                                               float& o0, float& o1) {
    const uint32_t P[4] = {1u, 2654435761u, 805459861u, 3674351687u};
    float fr[4], omf[4];
    uint32_t k0[4], k1[4];
#pragma unroll
    for (int d = 0; d < 4; d++) {
        float p = in4[d] * scale + 0.5f;
        float g = floorf(p);
        fr[d] = p - g;
        omf[d] = 1.0f - fr[d];
        uint32_t gi = (uint32_t)(int)g;
        k0[d] = gi * P[d];
        k1[d] = k0[d] + P[d];
    }
    float f0 = 0.0f, f1 = 0.0f;
#pragma unroll
    for (int c = 0; c < 16; c++) {
        uint32_t h = (((c & 1) ? k1[0] : k0[0]) ^ ((c & 2) ? k1[1] : k0[1]) ^
                      ((c & 4) ? k1[2] : k0[2]) ^ ((c & 8) ? k1[3] : k0[3]));
        uint32_t idx = h & TMASK;
        float w = ((c & 1) ? fr[0] : omf[0]) * ((c & 2) ? fr[1] : omf[1]) *
                  ((c & 4) ? fr[2] : omf[2]) * ((c & 8) ? fr[3] : omf[3]);
        float2 v = __ldg(&gt[idx]);
        f0 = fmaf(w, v.x, f0);
        f1 = fmaf(w, v.y, f1);
    }
    o0 = f0;
    o1 = f1;
}

__global__ void __launch_bounds__(BLOCK, 4)
htrf_kernel(const float4* __restrict__ xyzs,   // [N,4]
            const float* __restrict__ dirs,    // [N,3]
            const float2* __restrict__ grid,   // [L,T] of float2
            float* __restrict__ out,           // [N*3 color | N sigma]
            int N, Scales sc) {
    // 16-byte views over the constant bank: each ulonglong2 field is a packed
    // f32x2 pair (adjacent floats), used directly as fma.rn.f32x2 operands.
    const ulonglong2* __restrict__ w1v   = reinterpret_cast<const ulonglong2*>(cW);          // 64 rows x 8
    const ulonglong2* __restrict__ w2v   = reinterpret_cast<const ulonglong2*>(cW + 2048);   // 64 x 4
    const ulonglong2* __restrict__ wc1v  = reinterpret_cast<const ulonglong2*>(cW + 3072);   // 64 rows x 8
    const ulonglong2* __restrict__ wc2v  = reinterpret_cast<const ulonglong2*>(cW + 5120);   // 64 x 16
    const float4*     __restrict__ wc3t  = reinterpret_cast<const float4*>(cW + 9216);       // 64

    int t = blockIdx.x * BLOCK + threadIdx.x;
    if (t >= N) return;

    float4 xin = __ldg(&xyzs[t]);
    float in4[4];
    in4[0] = (xin.x + 1.0f) * 0.5f;
    in4[1] = (xin.y + 1.0f) * 0.5f;
    in4[2] = (xin.z + 1.0f) * 0.5f;
    in4[3] = xin.w;

    // ---- hash encode: hr packed as 16 f32x2 (level l -> pair (2l, 2l+1)) ----
    u64 hr2[16];
    {
        float o0, o1;
        enc_level_dense<8>(in4, sc.s[0], grid + 0 * TBL, o0, o1);  hr2[0] = pack2(o0, o1);
        enc_level_dense<12>(in4, sc.s[1], grid + 1 * TBL, o0, o1); hr2[1] = pack2(o0, o1);
        enc_level_dense<17>(in4, sc.s[2], grid + 2 * TBL, o0, o1); hr2[2] = pack2(o0, o1);
        enc_level_dense<25>(in4, sc.s[3], grid + 3 * TBL, o0, o1); hr2[3] = pack2(o0, o1);
#pragma unroll
        for (int l = 4; l < L_LEVELS; l++) {
            enc_level_hash(in4, sc.s[l], grid + l * TBL, o0, o1);
            hr2[l] = pack2(o0, o1);
        }
    }

    // ---- density MLP (packed): h16p[j] holds (h16[2j], h16[2j+1]) ----
    u64 h16p[8];
#pragma unroll
    for (int j = 0; j < 8; j++) h16p[j] = 0ull;
#pragma unroll 1
    for (int k = 0; k < 64; k++) {
        u64 vv = 0ull;
#pragma unroll
        for (int q = 0; q < 8; q++) {
            ulonglong2 w = w1v[k * 8 + q];
            fma2(vv, hr2[2 * q + 0], w.x);
            fma2(vv, hr2[2 * q + 1], w.y);
        }
        float vlo, vhi;
        unpack2(vv, vlo, vhi);
        float v = relu(vlo + vhi);
        u64 vp = pack2(v, v);
#pragma unroll
        for (int q = 0; q < 4; q++) {
            ulonglong2 w = w2v[k * 4 + q];
            fma2(h16p[2 * q + 0], vp, w.x);
            fma2(h16p[2 * q + 1], vp, w.y);
        }
    }
    float h16_0, h16_1;
    unpack2(h16p[0], h16_0, h16_1);
    float sigma = __expf(h16_0);

    // ---- spherical harmonics deg 4, packed into 8 f32x2 ----
    float dx = __ldg(&dirs[3 * t + 0]) * 2.0f - 1.0f;
    float dy = __ldg(&dirs[3 * t + 1]) * 2.0f - 1.0f;
    float dz = __ldg(&dirs[3 * t + 2]) * 2.0f - 1.0f;
    float xy = dx * dy, xz = dx * dz, yz = dy * dz;
    float x2 = dx * dx, y2 = dy * dy, z2 = dz * dz;
    u64 sh2[8];
    sh2[0] = pack2(0.28209479177387814f, -0.48860251190291987f * dy);
    sh2[1] = pack2(0.48860251190291987f * dz, -0.48860251190291987f * dx);
    sh2[2] = pack2(1.0925484305920792f * xy, -1.0925484305920792f * yz);
    sh2[3] = pack2(0.94617469575756f * z2 - 0.31539156525252f,
                   -1.0925484305920792f * xz);
    sh2[4] = pack2(0.5462742152960396f * x2 - 0.5462742152960396f * y2,
                   0.5900435899266435f * dy * (-3.0f * x2 + y2));
    sh2[5] = pack2(2.890611442640554f * xy * dz,
                   0.4570457994644657f * dy * (1.0f - 5.0f * z2));
    sh2[6] = pack2(0.3731763325901154f * dz * (5.0f * z2 - 3.0f),
                   0.4570457994644657f * dx * (1.0f - 5.0f * z2));
    sh2[7] = pack2(1.445305721320277f * dz * (x2 - y2),
                   0.5900435899266435f * dx * (-x2 + 3.0f * y2));

    // ---- color MLP (packed): a2p[j] holds (a2[2j], a2[2j+1]) ----
    u64 a2p[32];
#pragma unroll
    for (int j = 0; j < 32; j++) a2p[j] = 0ull;
#pragma unroll 1
    for (int k = 0; k < 64; k++) {
        u64 vv = 0ull;
#pragma unroll
        for (int q = 0; q < 4; q++) {
            ulonglong2 w = wc1v[k * 8 + q];
            fma2(vv, sh2[2 * q + 0], w.x);
            fma2(vv, sh2[2 * q + 1], w.y);
        }
#pragma unroll
        for (int q = 0; q < 4; q++) {
            ulonglong2 w = wc1v[k * 8 + 4 + q];
            fma2(vv, h16p[2 * q + 0], w.x);
            fma2(vv, h16p[2 * q + 1], w.y);
        }
        float vlo, vhi;
        unpack2(vv, vlo, vhi);
        float v = relu(vlo + vhi);
        u64 vp = pack2(v, v);
#pragma unroll
        for (int q = 0; q < 16; q++) {
            ulonglong2 w = wc2v[k * 16 + q];
            fma2(a2p[2 * q + 0], vp, w.x);
            fma2(a2p[2 * q + 1], vp, w.y);
        }
    }

    float c0 = 0.0f, c1 = 0.0f, c2 = 0.0f;
#pragma unroll 1
    for (int kk = 0; kk < 32; kk++) {
        float vlo, vhi;
        unpack2(a2p[kk], vlo, vhi);
        float va = relu(vlo), vb = relu(vhi);
        float4 wa = wc3t[2 * kk + 0];
        float4 wb = wc3t[2 * kk + 1];
        c0 = fmaf(va, wa.x, c0); c0 = fmaf(vb, wb.x, c0);
        c1 = fmaf(va, wa.y, c1); c1 = fmaf(vb, wb.y, c1);
        c2 = fmaf(va, wa.z, c2); c2 = fmaf(vb, wb.z, c2);
    }
    c0 = 1.0f / (1.0f + __expf(-c0));
    c1 = 1.0f / (1.0f + __expf(-c1));
    c2 = 1.0f / (1.0f + __expf(-c2));

    out[t * 3 + 0] = c0;
    out[t * 3 + 1] = c1;
    out[t * 3 + 2] = c2;
    out[3 * N + t] = sigma;
}

extern "C" void kernel_launch(void* const* d_in, const int* in_sizes, int n_in,
                              void* d_out, int out_size) {
    const float4* xyzs = (const float4*)d_in[0];
    const float* dirs = (const float*)d_in[1];
    const float2* grid = (const float2*)d_in[2];
    const float* W1 = (const float*)d_in[3];
    const float* W2 = (const float*)d_in[4];
    const float* Wc1 = (const float*)d_in[5];
    const float* Wc2 = (const float*)d_in[6];
    const float* Wc3 = (const float*)d_in[7];
    float* out = (float*)d_out;

    int N = in_sizes[0] / 4;

    Scales sc;
    const double log2B = log(2048.0 / 8.0) / 15.0 / log(2.0);  // = 8/15
    for (int l = 0; l < L_LEVELS; l++) {
        double scale = exp2((double)l * log2B) * 8.0 - 1.0;
        sc.s[l] = (float)scale;
    }

    // 1) transpose/pack weights into device scratch
    prep_kernel<<<16, 256>>>(W1, W2, Wc1, Wc2, Wc3);

    // 2) D2D copy into the constant bank (graph-capturable memcpy node)
    void* scratch_addr = nullptr;
    cudaGetSymbolAddress(&scratch_addr, g_scratch);
    cudaMemcpyToSymbolAsync(cW, scratch_addr, CW_TOTAL * sizeof(float), 0,
                            cudaMemcpyDeviceToDevice, 0);

    // 3) main fused kernel
    int blocks = (N + BLOCK - 1) / BLOCK;
    htrf_kernel<<<blocks, BLOCK>>>(xyzs, dirs, grid, out, N, sc);
}